// round 16
// baseline (speedup 1.0000x reference)
#include <cuda_runtime.h>
#include <cuda_fp16.h>
#include <math.h>
#include <stdint.h>

// Problem constants
constexpr int Bb   = 2;
constexpr int Nn   = 2048;
constexpr int Cc_  = 1024;
constexpr int Hh   = 16;
constexpr int HD   = 64;
constexpr int HID  = 4096;
constexpr int MTOK = Bb * Nn;            // 4096 token rows
constexpr float SCALE = 0.125f;          // 64^-0.5

// Scratch (static device allocations; no cudaMalloc allowed)
__device__ __half g_qkv [(size_t)MTOK * 3 * Cc_];   // 24 MB
__device__ __half g_ctx [(size_t)MTOK * Cc_];       //  8 MB
__device__ float  g_res [(size_t)MTOK * Cc_];       // 16 MB fp32 residual
__device__ __half g_resr[(size_t)MTOK * Cc_];       //  8 MB half copy
__device__ __half g_h   [(size_t)MTOK * HID];       // 32 MB
__device__ float  g_mlp [(size_t)MTOK * Cc_];       // 16 MB fp32
__device__ __half g_xh  [(size_t)MTOK * Cc_];       //  8 MB half x
__device__ __half g_w1  [(size_t)3 * Cc_ * Cc_];    //  6 MB
__device__ __half g_w2  [(size_t)Cc_ * Cc_];        //  2 MB
__device__ __half g_w3  [(size_t)HID * Cc_];        //  8 MB
__device__ __half g_w4  [(size_t)Cc_ * HID];        //  8 MB

// ===========================================================================
// helpers
// ===========================================================================
__device__ __forceinline__ uint32_t smem_u32(const void* p) {
    uint32_t a;
    asm("{ .reg .u64 t; cvta.to.shared.u64 t, %1; cvt.u32.u64 %0, t; }"
        : "=r"(a) : "l"(p));
    return a;
}
__device__ __forceinline__ void cp_async16(uint32_t dst, const void* src) {
    asm volatile("cp.async.cg.shared.global [%0], [%1], 16;"
                 :: "r"(dst), "l"(src));
}
#define CP_COMMIT() asm volatile("cp.async.commit_group;" ::: "memory")
#define CP_WAIT1()  asm volatile("cp.async.wait_group 1;" ::: "memory")
#define CP_WAIT2()  asm volatile("cp.async.wait_group 2;" ::: "memory")

#define LDSM4(r, a) \
    asm volatile("ldmatrix.sync.aligned.m8n8.x4.shared.b16 {%0,%1,%2,%3}, [%4];" \
        : "=r"((r)[0]), "=r"((r)[1]), "=r"((r)[2]), "=r"((r)[3]) : "r"(a))
#define LDSM2(r, a) \
    asm volatile("ldmatrix.sync.aligned.m8n8.x2.shared.b16 {%0,%1}, [%2];" \
        : "=r"((r)[0]), "=r"((r)[1]) : "r"(a))
#define LDSM2T(r, a) \
    asm volatile("ldmatrix.sync.aligned.m8n8.x2.trans.shared.b16 {%0,%1}, [%2];" \
        : "=r"((r)[0]), "=r"((r)[1]) : "r"(a))

// bit-reinterpret __half2 -> uint32_t (compiles to nothing)
__device__ __forceinline__ uint32_t h2_as_u32(__half2 h) {
    uint32_t u;
    *reinterpret_cast<__half2*>(&u) = h;
    return u;
}

// mma.sync m16n8k16 f16, fp32 accumulate
__device__ __forceinline__ void mma_f16(float* c, const uint32_t* a,
                                        const uint32_t* b) {
    asm volatile(
        "mma.sync.aligned.m16n8k16.row.col.f32.f16.f16.f32 "
        "{%0,%1,%2,%3}, {%4,%5,%6,%7}, {%8,%9}, {%0,%1,%2,%3};"
        : "+f"(c[0]), "+f"(c[1]), "+f"(c[2]), "+f"(c[3])
        : "r"(a[0]), "r"(a[1]), "r"(a[2]), "r"(a[3]),
          "r"(b[0]), "r"(b[1]));
}

__device__ __forceinline__ float gelu_exact(float v) {
    return 0.5f * v * (1.0f + erff(v * 0.70710678118654752f));
}

// ---------------------------------------------------------------------------
// Fused fp16 conversion: all 5 operand tensors in ONE launch.
// ---------------------------------------------------------------------------
constexpr int C4_X  = MTOK * Cc_ / 4;          // 1048576
constexpr int C4_W1 = 3 * Cc_ * Cc_ / 4;       //  786432
constexpr int C4_W2 = Cc_ * Cc_ / 4;           //  262144
constexpr int C4_W3 = HID * Cc_ / 4;           // 1048576
constexpr int C4_W4 = C4_W3;                   // 1048576
constexpr int C4_B0 = C4_X;
constexpr int C4_B1 = C4_B0 + C4_W1;
constexpr int C4_B2 = C4_B1 + C4_W2;
constexpr int C4_B3 = C4_B2 + C4_W3;
constexpr int C4_TOT = C4_B3 + C4_W4;          // 4194304
constexpr int CONV_BLOCKS = C4_TOT / 2 / 256;  // 8192

__global__ __launch_bounds__(256)
void to_half_all(const float* __restrict__ x,  const float* __restrict__ a1,
                 const float* __restrict__ a2, const float* __restrict__ a3,
                 const float* __restrict__ a4,
                 __half* __restrict__ xo, __half* __restrict__ o1,
                 __half* __restrict__ o2, __half* __restrict__ o3,
                 __half* __restrict__ o4)
{
    const int i8 = blockIdx.x * 256 + threadIdx.x;   // 8-float unit
    const int i4 = i8 * 2;                           // float4 unit (even)
    const float* src; __half* dst; int off4;
    if (i4 < C4_B0)      { src = x;  dst = xo; off4 = i4; }
    else if (i4 < C4_B1) { src = a1; dst = o1; off4 = i4 - C4_B0; }
    else if (i4 < C4_B2) { src = a2; dst = o2; off4 = i4 - C4_B1; }
    else if (i4 < C4_B3) { src = a3; dst = o3; off4 = i4 - C4_B2; }
    else                 { src = a4; dst = o4; off4 = i4 - C4_B3; }
    float4 v0 = ((const float4*)src)[off4];
    float4 v1 = ((const float4*)src)[off4 + 1];
    __half2 h[4];
    h[0] = __floats2half2_rn(v0.x, v0.y);
    h[1] = __floats2half2_rn(v0.z, v0.w);
    h[2] = __floats2half2_rn(v1.x, v1.y);
    h[3] = __floats2half2_rn(v1.z, v1.w);
    *(uint4*)((__half2*)dst + off4 * 2) = *(uint4*)h;
}

// ===========================================================================
// fp16 mma.sync GEMM (NT), occupancy-3 variant.
// CTA tile 128x64, BK=64 halves, 256 threads (8 warps 4x2), warp tile 32x32
// (acc 32 regs). 2-slot double buffer, 2 syncs (R10-proven shape).
// B fragments via paired LDSM4 (2 per kk instead of 4 LDSM2).
// pitch 72 halves (144B). OUT: 0 = f32, 2 = f16.
// ===========================================================================
constexpr int GBM = 128, GBN = 64, HBK = 64;
constexpr int HPITCH = HBK + 8;                      // 72 halves = 144 B
constexpr int A_STG = GBM * HPITCH;                  // 9216 halves = 18432 B
constexpr int B_STG = GBN * HPITCH;                  // 4608 halves =  9216 B
constexpr int NSTG = 2;
constexpr int GEMM_SMEM = NSTG * (A_STG + B_STG) * 2;   // 55296 B

template<int EPI, int OUT>
__global__ __launch_bounds__(256, 3)
void h_gemm(const __half* __restrict__ A, const __half* __restrict__ Bw,
            const float* __restrict__ bias, void* __restrict__ Co,
            int M, int N, int K)
{
    extern __shared__ __half smemh[];
    __half* As = smemh;                       // 2 stages
    __half* Bs = smemh + NSTG * A_STG;        // 2 stages
    const uint32_t As_u = smem_u32(As);
    const uint32_t Bs_u = smem_u32(Bs);

    const int tid = threadIdx.x;
    const int wid = tid >> 5;
    const int lid = tid & 31;
    const int g   = lid >> 2;
    const int tig = lid & 3;
    const int wm  = (wid & 3) * 32;          // 4 M-slots
    const int wn  = (wid >> 2) * 32;         // 2 N-slots
    const int m0  = blockIdx.y * GBM;
    const int n0  = blockIdx.x * GBN;
    const int NC  = K / HBK;

    // ldmatrix lane addressing (byte offsets within a stage)
    const uint32_t a_lane = (uint32_t)((wm + (lid & 15)) * 144 + (lid >> 4) * 16);
    // paired-B LDSM4: lanes 0-7 rows of nf0@k0, 8-15 nf0@k1, 16-23 nf1@k0, 24-31 nf1@k1
    const uint32_t b_lane = (uint32_t)((wn + ((lid >> 4) << 3) + (lid & 7)) * 144
                                       + ((lid >> 3) & 1) * 16);

    float acc[2][4][4];
    #pragma unroll
    for (int i = 0; i < 2; ++i)
        #pragma unroll
        for (int j = 0; j < 4; ++j)
            #pragma unroll
            for (int t = 0; t < 4; ++t) acc[i][j][t] = 0.f;

    // chunk load: A 128 rows + B 64 rows, 8 16B-chunks each = 1536; 6/thread
    auto load_chunk = [&](int kc, int st) {
        const int k0h = kc * HBK;
        const uint32_t abase = As_u + st * A_STG * 2;
        const uint32_t bbase = Bs_u + st * B_STG * 2;
        #pragma unroll
        for (int t = 0; t < 6; ++t) {
            int idx = tid + t * 256;          // 0..1535
            int r   = idx >> 3;               // 0..191
            int c   = idx & 7;
            if (r < GBM) {
                cp_async16(abase + (uint32_t)(r * 144 + c * 16),
                           A + (size_t)(m0 + r) * K + k0h + c * 8);
            } else {
                int rb = r - GBM;
                cp_async16(bbase + (uint32_t)(rb * 144 + c * 16),
                           Bw + (size_t)(n0 + rb) * K + k0h + c * 8);
            }
        }
        CP_COMMIT();
    };

    load_chunk(0, 0);
    load_chunk(1, 1);

    for (int i = 0; i < NC; ++i) {
        const int st = i & 1;
        CP_WAIT1();
        __syncthreads();

        const uint32_t Ast = As_u + st * A_STG * 2;
        const uint32_t Bst = Bs_u + st * B_STG * 2;

        #pragma unroll
        for (int kk = 0; kk < 4; ++kk) {           // 4 x K=16
            uint32_t af[2][4], bq[2][4];
            #pragma unroll
            for (int mf = 0; mf < 2; ++mf)
                LDSM4(af[mf], Ast + a_lane + mf * 16 * 144 + kk * 32);
            #pragma unroll
            for (int np = 0; np < 2; ++np)
                LDSM4(bq[np], Bst + b_lane + np * 16 * 144 + kk * 32);
            #pragma unroll
            for (int mf = 0; mf < 2; ++mf)
                #pragma unroll
                for (int np = 0; np < 2; ++np) {
                    mma_f16(acc[mf][2 * np + 0], af[mf], &bq[np][0]);
                    mma_f16(acc[mf][2 * np + 1], af[mf], &bq[np][2]);
                }
        }

        __syncthreads();
        if (i + 2 < NC) load_chunk(i + 2, st);
        else            CP_COMMIT();
    }

    #pragma unroll
    for (int mf = 0; mf < 2; ++mf) {
        const int r0 = m0 + wm + mf * 16 + g;
        const int r1 = r0 + 8;
        #pragma unroll
        for (int nf = 0; nf < 4; ++nf) {
            const int col = n0 + wn + nf * 8 + tig * 2;
            float b0 = 0.f, b1 = 0.f;
            if (bias) { b0 = bias[col]; b1 = bias[col + 1]; }
            float t0 = acc[mf][nf][0] + b0;
            float t1 = acc[mf][nf][1] + b1;
            float t2 = acc[mf][nf][2] + b0;
            float t3 = acc[mf][nf][3] + b1;
            if (EPI == 1) {
                t0 = gelu_exact(t0); t1 = gelu_exact(t1);
                t2 = gelu_exact(t2); t3 = gelu_exact(t3);
            }
            if (OUT == 0) {
                float* Cf = (float*)Co;
                float2 v0; v0.x = t0; v0.y = t1;
                float2 v1; v1.x = t2; v1.y = t3;
                *(float2*)(Cf + (size_t)r0 * N + col) = v0;
                *(float2*)(Cf + (size_t)r1 * N + col) = v1;
            } else {
                __half* Ch = (__half*)Co;
                *(__half2*)(Ch + (size_t)r0 * N + col) = __floats2half2_rn(t0, t1);
                *(__half2*)(Ch + (size_t)r1 * N + col) = __floats2half2_rn(t2, t3);
            }
        }
    }
}

// ===========================================================================
// Flash attention, fp16 m16n8k16, one-barrier 3-slot K/V pipeline (R12).
// 128 q rows/CTA (8 warps x 16), 64-key tiles, pitch 72 halves.
// ===========================================================================
constexpr int AQ   = 128;
constexpr int AKT  = 64;
constexpr int APiH = 72;
constexpr int A_KOFF = AQ * APiH;                    // halves
constexpr int A_VOFF = A_KOFF + 3 * AKT * APiH;
constexpr int ATT_SMEM = (A_VOFF + 3 * AKT * APiH) * 2;   // 73728 B

__global__ __launch_bounds__(256, 2)
void attn_h(const __half* __restrict__ qkv, __half* __restrict__ ctx)
{
    extern __shared__ __half smh[];
    __half* Qs = smh;
    __half* Ks = smh + A_KOFF;
    __half* Vs = smh + A_VOFF;
    const uint32_t Qs_u = smem_u32(Qs);
    const uint32_t Ks_u = smem_u32(Ks);
    const uint32_t Vs_u = smem_u32(Vs);

    const int tid = threadIdx.x;
    const int wid = tid >> 5;
    const int lid = tid & 31;
    const int g   = lid >> 2;
    const int tig = lid & 3;
    const int q0  = blockIdx.x * AQ;
    const int h   = blockIdx.y;
    const int b   = blockIdx.z;
    const int wq  = wid * 16;

    const size_t tok0 = (size_t)(b * Nn);
    const int hoff = h * HD;

    // ldmatrix lane addressing (byte offsets)
    const uint32_t q_lane = (uint32_t)((wq + (lid & 15)) * 144 + (lid >> 4) * 16);
    const uint32_t k_lane = (uint32_t)((lid & 7) * 144 + ((lid >> 3) & 1) * 16);
    const uint32_t v_lane = (uint32_t)((lid & 15) * 144);

    // Q tile: 128 rows x 8 chunks = 1024; 4/thread  (own cp.async group)
    #pragma unroll
    for (int t = 0; t < 4; ++t) {
        int idx = tid + t * 256;
        int r = idx >> 3, c = idx & 7;
        cp_async16(Qs_u + (uint32_t)(r * 144 + c * 16),
                   qkv + (tok0 + q0 + r) * (3 * Cc_) + hoff + c * 8);
    }
    CP_COMMIT();

    auto load_tile = [&](int kt, int st) {
        const int k0 = kt * AKT;
        const uint32_t kb = Ks_u + (uint32_t)(st * AKT * APiH) * 2;
        const uint32_t vb = Vs_u + (uint32_t)(st * AKT * APiH) * 2;
        #pragma unroll
        for (int t = 0; t < 2; ++t) {
            int idx = tid + t * 256;
            int r = idx >> 3, c = idx & 7;
            const __half* src = qkv + (tok0 + k0 + r) * (3 * Cc_) + Cc_ + hoff + c * 8;
            uint32_t off = (uint32_t)(r * 144 + c * 16);
            cp_async16(kb + off, src);
            cp_async16(vb + off, src + Cc_);
        }
        CP_COMMIT();
    };
    load_tile(0, 0);
    load_tile(1, 1);

    CP_WAIT2();            // Q resident (tiles 0,1 may be in flight)
    __syncthreads();

    // Q fragments: 4 chunks of K=16
    uint32_t qf[4][4];
    #pragma unroll
    for (int kk = 0; kk < 4; ++kk)
        LDSM4(qf[kk], Qs_u + q_lane + kk * 32);

    float o[8][4];
    #pragma unroll
    for (int d = 0; d < 8; ++d)
        #pragma unroll
        for (int t = 0; t < 4; ++t) o[d][t] = 0.f;
    float m0 = -1e30f, m1 = -1e30f, l0 = 0.f, l1 = 0.f;

    const int NT = Nn / AKT;     // 32
    int cst = 0, lst = 2;
    for (int it = 0; it < NT; ++it) {
        CP_WAIT1();
        __syncthreads();

        if (it + 2 < NT) load_tile(it + 2, lst);
        else             CP_COMMIT();
        lst = (lst == 2) ? 0 : lst + 1;

        const uint32_t Kb = Ks_u + (uint32_t)(cst * AKT * APiH) * 2;
        const uint32_t Vb = Vs_u + (uint32_t)(cst * AKT * APiH) * 2;

        // ---- S = Q K^T  (8 key-chunks of 8) ----
        float s[8][4];
        #pragma unroll
        for (int nf = 0; nf < 8; ++nf) {
            s[nf][0] = 0.f; s[nf][1] = 0.f; s[nf][2] = 0.f; s[nf][3] = 0.f;
            const uint32_t kaddr = Kb + k_lane + nf * 8 * 144;
            #pragma unroll
            for (int kk = 0; kk < 4; ++kk) {
                uint32_t bf[2];
                LDSM2(bf, kaddr + kk * 32);
                mma_f16(s[nf], qf[kk], bf);
            }
            s[nf][0] *= SCALE; s[nf][1] *= SCALE;
            s[nf][2] *= SCALE; s[nf][3] *= SCALE;
        }

        // ---- softmax update ----
        float t0 = -1e30f, t1 = -1e30f;
        #pragma unroll
        for (int nf = 0; nf < 8; ++nf) {
            t0 = fmaxf(t0, fmaxf(s[nf][0], s[nf][1]));
            t1 = fmaxf(t1, fmaxf(s[nf][2], s[nf][3]));
        }
        t0 = fmaxf(t0, __shfl_xor_sync(0xffffffff, t0, 1));
        t0 = fmaxf(t0, __shfl_xor_sync(0xffffffff, t0, 2));
        t1 = fmaxf(t1, __shfl_xor_sync(0xffffffff, t1, 1));
        t1 = fmaxf(t1, __shfl_xor_sync(0xffffffff, t1, 2));
        const float nm0 = fmaxf(m0, t0), nm1 = fmaxf(m1, t1);
        const float c0 = __expf(m0 - nm0), c1 = __expf(m1 - nm1);
        m0 = nm0; m1 = nm1;
        l0 *= c0; l1 *= c1;
        #pragma unroll
        for (int d = 0; d < 8; ++d) {
            o[d][0] *= c0; o[d][1] *= c0;
            o[d][2] *= c1; o[d][3] *= c1;
        }

        // ---- P = exp(S-m) packed directly into k16 A-fragments ----
        uint32_t pa[4][4];
        #pragma unroll
        for (int nf = 0; nf < 8; ++nf) {
            float p0 = __expf(s[nf][0] - m0);
            float p1 = __expf(s[nf][1] - m0);
            float p2 = __expf(s[nf][2] - m1);
            float p3 = __expf(s[nf][3] - m1);
            l0 += p0 + p1;
            l1 += p2 + p3;
            pa[nf >> 1][2 * (nf & 1) + 0] = h2_as_u32(__floats2half2_rn(p0, p1));
            pa[nf >> 1][2 * (nf & 1) + 1] = h2_as_u32(__floats2half2_rn(p2, p3));
        }

        // ---- O += P V  (V^T fragments via ldmatrix.trans) ----
        #pragma unroll
        for (int kt2 = 0; kt2 < 4; ++kt2) {
            const uint32_t vbase = Vb + v_lane + kt2 * 16 * 144;
            #pragma unroll
            for (int df = 0; df < 8; ++df) {
                uint32_t bf[2];
                LDSM2T(bf, vbase + df * 16);
                mma_f16(o[df], pa[kt2], bf);
            }
        }

        cst = (cst == 2) ? 0 : cst + 1;
    }

    l0 += __shfl_xor_sync(0xffffffff, l0, 1);
    l0 += __shfl_xor_sync(0xffffffff, l0, 2);
    l1 += __shfl_xor_sync(0xffffffff, l1, 1);
    l1 += __shfl_xor_sync(0xffffffff, l1, 2);
    const float inv0 = 1.f / l0, inv1 = 1.f / l1;
    const int qr0 = q0 + wq + g;
    const int qr1 = qr0 + 8;
    #pragma unroll
    for (int df = 0; df < 8; ++df) {
        *(__half2*)(ctx + (tok0 + qr0) * Cc_ + hoff + 8 * df + 2 * tig) =
            __floats2half2_rn(o[df][0] * inv0, o[df][1] * inv0);
        *(__half2*)(ctx + (tok0 + qr1) * Cc_ + hoff + 8 * df + 2 * tig) =
            __floats2half2_rn(o[df][2] * inv1, o[df][3] * inv1);
    }
}

// ---------------------------------------------------------------------------
// out[row] = res[row] + LayerNorm(x[row]) * w + b     (row length 1024)
// DUAL=1: also write __half copy to out_h.
// ---------------------------------------------------------------------------
template<int DUAL>
__global__ __launch_bounds__(256)
void ln_residual(const float* __restrict__ x, const float* __restrict__ res,
                 const float* __restrict__ w, const float* __restrict__ bp,
                 float* __restrict__ out, __half* __restrict__ out_h)
{
    __shared__ float red[256];
    const int row = blockIdx.x;
    const int tid = threadIdx.x;
    const size_t base = (size_t)row * Cc_;

    float4 v = *(const float4*)(x + base + tid * 4);
    float s = v.x + v.y + v.z + v.w;
    red[tid] = s;
    __syncthreads();
    #pragma unroll
    for (int off = 128; off > 0; off >>= 1) {
        if (tid < off) red[tid] += red[tid + off];
        __syncthreads();
    }
    const float mu = red[0] * (1.0f / Cc_);
    __syncthreads();

    float d0 = v.x - mu, d1 = v.y - mu, d2 = v.z - mu, d3 = v.w - mu;
    red[tid] = d0*d0 + d1*d1 + d2*d2 + d3*d3;
    __syncthreads();
    #pragma unroll
    for (int off = 128; off > 0; off >>= 1) {
        if (tid < off) red[tid] += red[tid + off];
        __syncthreads();
    }
    const float var  = red[0] * (1.0f / Cc_);
    const float rstd = rsqrtf(var + 1e-5f);

    float4 rv = *(const float4*)(res + base + tid * 4);
    float4 wv = *(const float4*)(w + tid * 4);
    float4 bv = *(const float4*)(bp + tid * 4);
    float4 ov;
    ov.x = rv.x + d0 * rstd * wv.x + bv.x;
    ov.y = rv.y + d1 * rstd * wv.y + bv.y;
    ov.z = rv.z + d2 * rstd * wv.z + bv.z;
    ov.w = rv.w + d3 * rstd * wv.w + bv.w;
    *(float4*)(out + base + tid * 4) = ov;
    if (DUAL == 1) {
        __half2* oh = (__half2*)(out_h + base + tid * 4);
        oh[0] = __floats2half2_rn(ov.x, ov.y);
        oh[1] = __floats2half2_rn(ov.z, ov.w);
    }
}

// ---------------------------------------------------------------------------
// Launch
// ---------------------------------------------------------------------------
extern "C" void kernel_launch(void* const* d_in, const int* in_sizes, int n_in,
                              void* d_out, int out_size)
{
    const float* x      = (const float*)d_in[0];
    const float* qkv_w  = (const float*)d_in[1];
    const float* proj_w = (const float*)d_in[2];
    const float* proj_b = (const float*)d_in[3];
    const float* ln1_w  = (const float*)d_in[4];
    const float* ln1_b  = (const float*)d_in[5];
    const float* fc1_w  = (const float*)d_in[6];
    const float* fc1_b  = (const float*)d_in[7];
    const float* fc2_w  = (const float*)d_in[8];
    const float* fc2_b  = (const float*)d_in[9];
    const float* ln2_w  = (const float*)d_in[10];
    const float* ln2_b  = (const float*)d_in[11];
    float* out = (float*)d_out;

    float *res, *mlp;
    __half *qkv, *ctx, *resr, *hbuf, *xh, *w1, *w2, *w3, *w4;
    cudaGetSymbolAddress((void**)&qkv,  g_qkv);
    cudaGetSymbolAddress((void**)&ctx,  g_ctx);
    cudaGetSymbolAddress((void**)&res,  g_res);
    cudaGetSymbolAddress((void**)&resr, g_resr);
    cudaGetSymbolAddress((void**)&hbuf, g_h);
    cudaGetSymbolAddress((void**)&mlp,  g_mlp);
    cudaGetSymbolAddress((void**)&xh,   g_xh);
    cudaGetSymbolAddress((void**)&w1,   g_w1);
    cudaGetSymbolAddress((void**)&w2,   g_w2);
    cudaGetSymbolAddress((void**)&w3,   g_w3);
    cudaGetSymbolAddress((void**)&w4,   g_w4);

    cudaFuncSetAttribute(h_gemm<0,0>,
        cudaFuncAttributeMaxDynamicSharedMemorySize, GEMM_SMEM);
    cudaFuncSetAttribute(h_gemm<0,2>,
        cudaFuncAttributeMaxDynamicSharedMemorySize, GEMM_SMEM);
    cudaFuncSetAttribute(h_gemm<1,2>,
        cudaFuncAttributeMaxDynamicSharedMemorySize, GEMM_SMEM);
    cudaFuncSetAttribute(attn_h,
        cudaFuncAttributeMaxDynamicSharedMemorySize, ATT_SMEM);

    // 0) one fused fp16 conversion pass for all GEMM operands
    to_half_all<<<CONV_BLOCKS, 256>>>(x, qkv_w, proj_w, fc1_w, fc2_w,
                                      xh, w1, w2, w3, w4);

    // 1) qkv = x @ qkv_w^T  (half out)
    h_gemm<0,2><<<dim3(3 * Cc_ / GBN, MTOK / GBM), 256, GEMM_SMEM>>>(
        xh, w1, nullptr, qkv, MTOK, 3 * Cc_, Cc_);
    // 2) attention -> ctx (half)
    attn_h<<<dim3(Nn / AQ, Hh, Bb), 256, ATT_SMEM>>>(qkv, ctx);
    // 3) res = ctx @ proj_w^T + proj_b  (fp32 residual base)
    h_gemm<0,0><<<dim3(Cc_ / GBN, MTOK / GBM), 256, GEMM_SMEM>>>(
        ctx, w2, proj_b, res, MTOK, Cc_, Cc_);
    // 4) res = res + LN(res); also half copy resr
    ln_residual<1><<<MTOK, 256>>>(res, res, ln1_w, ln1_b, res, resr);
    // 5) h = gelu(resr @ fc1_w^T + fc1_b)  (half out)
    h_gemm<1,2><<<dim3(HID / GBN, MTOK / GBM), 256, GEMM_SMEM>>>(
        resr, w3, fc1_b, hbuf, MTOK, HID, Cc_);
    // 6) mlp = h @ fc2_w^T + fc2_b  (fp32 out)
    h_gemm<0,0><<<dim3(Cc_ / GBN, MTOK / GBM), 256, GEMM_SMEM>>>(
        hbuf, w4, fc2_b, mlp, MTOK, Cc_, HID);
    // 7) out = res + LN(mlp)
    ln_residual<0><<<MTOK, 256>>>(mlp, res, ln2_w, ln2_b, out, nullptr);
}

// round 17
// speedup vs baseline: 1.0420x; 1.0420x over previous
#include <cuda_runtime.h>
#include <cuda_fp16.h>
#include <math.h>
#include <stdint.h>

// Problem constants
constexpr int Bb   = 2;
constexpr int Nn   = 2048;
constexpr int Cc_  = 1024;
constexpr int Hh   = 16;
constexpr int HD   = 64;
constexpr int HID  = 4096;
constexpr int MTOK = Bb * Nn;            // 4096 token rows
constexpr float SCALE = 0.125f;          // 64^-0.5

// Scratch (static device allocations; no cudaMalloc allowed)
__device__ __half g_qkv [(size_t)MTOK * 3 * Cc_];   // 24 MB
__device__ __half g_ctx [(size_t)MTOK * Cc_];       //  8 MB
__device__ float  g_res [(size_t)MTOK * Cc_];       // 16 MB fp32 residual
__device__ __half g_resr[(size_t)MTOK * Cc_];       //  8 MB half copy
__device__ __half g_h   [(size_t)MTOK * HID];       // 32 MB
__device__ float  g_mlp [(size_t)MTOK * Cc_];       // 16 MB fp32
__device__ __half g_xh  [(size_t)MTOK * Cc_];       //  8 MB half x
__device__ __half g_w1  [(size_t)3 * Cc_ * Cc_];    //  6 MB
__device__ __half g_w2  [(size_t)Cc_ * Cc_];        //  2 MB
__device__ __half g_w3  [(size_t)HID * Cc_];        //  8 MB
__device__ __half g_w4  [(size_t)Cc_ * HID];        //  8 MB

// ===========================================================================
// helpers
// ===========================================================================
__device__ __forceinline__ uint32_t smem_u32(const void* p) {
    uint32_t a;
    asm("{ .reg .u64 t; cvta.to.shared.u64 t, %1; cvt.u32.u64 %0, t; }"
        : "=r"(a) : "l"(p));
    return a;
}
__device__ __forceinline__ void cp_async16(uint32_t dst, const void* src) {
    asm volatile("cp.async.cg.shared.global [%0], [%1], 16;"
                 :: "r"(dst), "l"(src));
}
#define CP_COMMIT() asm volatile("cp.async.commit_group;" ::: "memory")
#define CP_WAIT0()  asm volatile("cp.async.wait_group 0;" ::: "memory")
#define CP_WAIT1()  asm volatile("cp.async.wait_group 1;" ::: "memory")
#define CP_WAIT2()  asm volatile("cp.async.wait_group 2;" ::: "memory")

#define LDSM4(r, a) \
    asm volatile("ldmatrix.sync.aligned.m8n8.x4.shared.b16 {%0,%1,%2,%3}, [%4];" \
        : "=r"((r)[0]), "=r"((r)[1]), "=r"((r)[2]), "=r"((r)[3]) : "r"(a))
#define LDSM2(r, a) \
    asm volatile("ldmatrix.sync.aligned.m8n8.x2.shared.b16 {%0,%1}, [%2];" \
        : "=r"((r)[0]), "=r"((r)[1]) : "r"(a))
#define LDSM2T(r, a) \
    asm volatile("ldmatrix.sync.aligned.m8n8.x2.trans.shared.b16 {%0,%1}, [%2];" \
        : "=r"((r)[0]), "=r"((r)[1]) : "r"(a))

// bit-reinterpret __half2 -> uint32_t (compiles to nothing)
__device__ __forceinline__ uint32_t h2_as_u32(__half2 h) {
    uint32_t u;
    *reinterpret_cast<__half2*>(&u) = h;
    return u;
}

// mma.sync m16n8k16 f16, fp32 accumulate
__device__ __forceinline__ void mma_f16(float* c, const uint32_t* a,
                                        const uint32_t* b) {
    asm volatile(
        "mma.sync.aligned.m16n8k16.row.col.f32.f16.f16.f32 "
        "{%0,%1,%2,%3}, {%4,%5,%6,%7}, {%8,%9}, {%0,%1,%2,%3};"
        : "+f"(c[0]), "+f"(c[1]), "+f"(c[2]), "+f"(c[3])
        : "r"(a[0]), "r"(a[1]), "r"(a[2]), "r"(a[3]),
          "r"(b[0]), "r"(b[1]));
}

__device__ __forceinline__ float gelu_exact(float v) {
    return 0.5f * v * (1.0f + erff(v * 0.70710678118654752f));
}

// ---------------------------------------------------------------------------
// Fused fp16 conversion: all 5 operand tensors in ONE launch.
// ---------------------------------------------------------------------------
constexpr int C4_X  = MTOK * Cc_ / 4;          // 1048576
constexpr int C4_W1 = 3 * Cc_ * Cc_ / 4;       //  786432
constexpr int C4_W2 = Cc_ * Cc_ / 4;           //  262144
constexpr int C4_W3 = HID * Cc_ / 4;           // 1048576
constexpr int C4_W4 = C4_W3;                   // 1048576
constexpr int C4_B0 = C4_X;
constexpr int C4_B1 = C4_B0 + C4_W1;
constexpr int C4_B2 = C4_B1 + C4_W2;
constexpr int C4_B3 = C4_B2 + C4_W3;
constexpr int C4_TOT = C4_B3 + C4_W4;          // 4194304
constexpr int CONV_BLOCKS = C4_TOT / 2 / 256;  // 8192

__global__ __launch_bounds__(256)
void to_half_all(const float* __restrict__ x,  const float* __restrict__ a1,
                 const float* __restrict__ a2, const float* __restrict__ a3,
                 const float* __restrict__ a4,
                 __half* __restrict__ xo, __half* __restrict__ o1,
                 __half* __restrict__ o2, __half* __restrict__ o3,
                 __half* __restrict__ o4)
{
    const int i8 = blockIdx.x * 256 + threadIdx.x;   // 8-float unit
    const int i4 = i8 * 2;                           // float4 unit (even)
    const float* src; __half* dst; int off4;
    if (i4 < C4_B0)      { src = x;  dst = xo; off4 = i4; }
    else if (i4 < C4_B1) { src = a1; dst = o1; off4 = i4 - C4_B0; }
    else if (i4 < C4_B2) { src = a2; dst = o2; off4 = i4 - C4_B1; }
    else if (i4 < C4_B3) { src = a3; dst = o3; off4 = i4 - C4_B2; }
    else                 { src = a4; dst = o4; off4 = i4 - C4_B3; }
    float4 v0 = ((const float4*)src)[off4];
    float4 v1 = ((const float4*)src)[off4 + 1];
    __half2 h[4];
    h[0] = __floats2half2_rn(v0.x, v0.y);
    h[1] = __floats2half2_rn(v0.z, v0.w);
    h[2] = __floats2half2_rn(v1.x, v1.y);
    h[3] = __floats2half2_rn(v1.z, v1.w);
    *(uint4*)((__half2*)dst + off4 * 2) = *(uint4*)h;
}

// ===========================================================================
// fp16 mma.sync GEMM (NT), PERSISTENT grid-stride over tiles.
// R12-proven mainloop: one-barrier 3-slot pipeline, 2 cp.async groups in
// flight, loads issued before compute. BM=BN=128, BK=64 halves, 256 threads
// (8 warps 2x4), warp tile 64x32, pitch 72 halves (144B).
// Tiles walked n-major so consecutive CTAs share the A tile-row in L2.
// OUT: 0 = f32, 2 = f16.
// ===========================================================================
constexpr int GBM = 128, GBN = 128, HBK = 64;
constexpr int HPITCH = HBK + 8;                     // 72 halves = 144 B
constexpr int STAGE_H = GBM * HPITCH;               // halves per operand stage
constexpr int NSTG = 3;
constexpr int GEMM_SMEM = NSTG * 2 * STAGE_H * 2;   // 110592 B
constexpr int PERS_CTAS = 296;                      // 148 SM x occ 2

template<int EPI, int OUT>
__global__ __launch_bounds__(256, 2)
void h_gemm(const __half* __restrict__ A, const __half* __restrict__ Bw,
            const float* __restrict__ bias, void* __restrict__ Co,
            int M, int N, int K)
{
    extern __shared__ __half smemh[];
    __half* As = smemh;
    __half* Bs = smemh + NSTG * STAGE_H;
    const uint32_t As_u = smem_u32(As);
    const uint32_t Bs_u = smem_u32(Bs);

    const int tid = threadIdx.x;
    const int wid = tid >> 5;
    const int lid = tid & 31;
    const int g   = lid >> 2;
    const int tig = lid & 3;
    const int wm  = (wid & 1) * 64;
    const int wn  = (wid >> 1) * 32;
    const int NC  = K / HBK;
    const int ntn = N / GBN;
    const int ntiles = (M / GBM) * ntn;

    // ldmatrix lane addressing (byte offsets within a stage)
    const uint32_t a_lane = (uint32_t)((wm + (lid & 15)) * 144 + (lid >> 4) * 16);
    const uint32_t b_lane = (uint32_t)((wn + (lid & 7)) * 144 + ((lid >> 3) & 1) * 16);

    for (int tile = blockIdx.x; tile < ntiles; tile += gridDim.x) {
        const int m0 = (tile / ntn) * GBM;
        const int n0 = (tile % ntn) * GBN;

        float acc[4][4][4];
        #pragma unroll
        for (int i = 0; i < 4; ++i)
            #pragma unroll
            for (int j = 0; j < 4; ++j)
                #pragma unroll
                for (int t = 0; t < 4; ++t) acc[i][j][t] = 0.f;

        auto load_chunk = [&](int kc, int st) {
            const int k0h = kc * HBK;
            const uint32_t abase = As_u + st * STAGE_H * 2;
            const uint32_t bbase = Bs_u + st * STAGE_H * 2;
            #pragma unroll
            for (int t = 0; t < 4; ++t) {
                int idx = tid + t * 256;
                int r   = idx >> 3;
                int c   = idx & 7;
                uint32_t off = (uint32_t)(r * 144 + c * 16);
                cp_async16(abase + off, A + (size_t)(m0 + r) * K + k0h + c * 8);
                cp_async16(bbase + off, Bw + (size_t)(n0 + r) * K + k0h + c * 8);
            }
            CP_COMMIT();
        };

        // seam: prior tile's compute reads must finish before slot reuse;
        // also drain stale cp.async groups so counts restart clean.
        CP_WAIT0();
        __syncthreads();

        load_chunk(0, 0);
        load_chunk(1, 1);

        int cst = 0;   // consume slot
        int lst = 2;   // load slot
        for (int i = 0; i < NC; ++i) {
            CP_WAIT1();             // chunk i resident
            __syncthreads();        // orders prior iter's reads before reuse

            // issue next loads FIRST (overlap DMA with MMA below)
            if (i + 2 < NC) load_chunk(i + 2, lst);
            else            CP_COMMIT();
            lst = (lst == NSTG - 1) ? 0 : lst + 1;

            const uint32_t Ast = As_u + cst * STAGE_H * 2;
            const uint32_t Bst = Bs_u + cst * STAGE_H * 2;

            #pragma unroll
            for (int kk = 0; kk < 4; ++kk) {           // 4 x K=16
                uint32_t af[4][4], bf[4][2];
                #pragma unroll
                for (int mf = 0; mf < 4; ++mf)
                    LDSM4(af[mf], Ast + a_lane + mf * 16 * 144 + kk * 32);
                #pragma unroll
                for (int nf = 0; nf < 4; ++nf)
                    LDSM2(bf[nf], Bst + b_lane + nf * 8 * 144 + kk * 32);
                #pragma unroll
                for (int mf = 0; mf < 4; ++mf)
                    #pragma unroll
                    for (int nf = 0; nf < 4; ++nf)
                        mma_f16(acc[mf][nf], af[mf], bf[nf]);
            }

            cst = (cst == NSTG - 1) ? 0 : cst + 1;
        }

        // epilogue (register-only; no smem reads)
        #pragma unroll
        for (int mf = 0; mf < 4; ++mf) {
            const int r0 = m0 + wm + mf * 16 + g;
            const int r1 = r0 + 8;
            #pragma unroll
            for (int nf = 0; nf < 4; ++nf) {
                const int col = n0 + wn + nf * 8 + tig * 2;
                float b0 = 0.f, b1 = 0.f;
                if (bias) { b0 = bias[col]; b1 = bias[col + 1]; }
                float t0 = acc[mf][nf][0] + b0;
                float t1 = acc[mf][nf][1] + b1;
                float t2 = acc[mf][nf][2] + b0;
                float t3 = acc[mf][nf][3] + b1;
                if (EPI == 1) {
                    t0 = gelu_exact(t0); t1 = gelu_exact(t1);
                    t2 = gelu_exact(t2); t3 = gelu_exact(t3);
                }
                if (OUT == 0) {
                    float* Cf = (float*)Co;
                    float2 v0; v0.x = t0; v0.y = t1;
                    float2 v1; v1.x = t2; v1.y = t3;
                    *(float2*)(Cf + (size_t)r0 * N + col) = v0;
                    *(float2*)(Cf + (size_t)r1 * N + col) = v1;
                } else {
                    __half* Ch = (__half*)Co;
                    *(__half2*)(Ch + (size_t)r0 * N + col) = __floats2half2_rn(t0, t1);
                    *(__half2*)(Ch + (size_t)r1 * N + col) = __floats2half2_rn(t2, t3);
                }
            }
        }
    }
}

// ===========================================================================
// Flash attention, fp16 m16n8k16, one-barrier 3-slot K/V pipeline (R12).
// 128 q rows/CTA (8 warps x 16), 64-key tiles, pitch 72 halves.
// ===========================================================================
constexpr int AQ   = 128;
constexpr int AKT  = 64;
constexpr int APiH = 72;
constexpr int A_KOFF = AQ * APiH;                    // halves
constexpr int A_VOFF = A_KOFF + 3 * AKT * APiH;
constexpr int ATT_SMEM = (A_VOFF + 3 * AKT * APiH) * 2;   // 73728 B

__global__ __launch_bounds__(256, 2)
void attn_h(const __half* __restrict__ qkv, __half* __restrict__ ctx)
{
    extern __shared__ __half smh[];
    __half* Qs = smh;
    __half* Ks = smh + A_KOFF;
    __half* Vs = smh + A_VOFF;
    const uint32_t Qs_u = smem_u32(Qs);
    const uint32_t Ks_u = smem_u32(Ks);
    const uint32_t Vs_u = smem_u32(Vs);

    const int tid = threadIdx.x;
    const int wid = tid >> 5;
    const int lid = tid & 31;
    const int g   = lid >> 2;
    const int tig = lid & 3;
    const int q0  = blockIdx.x * AQ;
    const int h   = blockIdx.y;
    const int b   = blockIdx.z;
    const int wq  = wid * 16;

    const size_t tok0 = (size_t)(b * Nn);
    const int hoff = h * HD;

    // ldmatrix lane addressing (byte offsets)
    const uint32_t q_lane = (uint32_t)((wq + (lid & 15)) * 144 + (lid >> 4) * 16);
    const uint32_t k_lane = (uint32_t)((lid & 7) * 144 + ((lid >> 3) & 1) * 16);
    const uint32_t v_lane = (uint32_t)((lid & 15) * 144);

    // Q tile: 128 rows x 8 chunks = 1024; 4/thread  (own cp.async group)
    #pragma unroll
    for (int t = 0; t < 4; ++t) {
        int idx = tid + t * 256;
        int r = idx >> 3, c = idx & 7;
        cp_async16(Qs_u + (uint32_t)(r * 144 + c * 16),
                   qkv + (tok0 + q0 + r) * (3 * Cc_) + hoff + c * 8);
    }
    CP_COMMIT();

    auto load_tile = [&](int kt, int st) {
        const int k0 = kt * AKT;
        const uint32_t kb = Ks_u + (uint32_t)(st * AKT * APiH) * 2;
        const uint32_t vb = Vs_u + (uint32_t)(st * AKT * APiH) * 2;
        #pragma unroll
        for (int t = 0; t < 2; ++t) {
            int idx = tid + t * 256;
            int r = idx >> 3, c = idx & 7;
            const __half* src = qkv + (tok0 + k0 + r) * (3 * Cc_) + Cc_ + hoff + c * 8;
            uint32_t off = (uint32_t)(r * 144 + c * 16);
            cp_async16(kb + off, src);
            cp_async16(vb + off, src + Cc_);
        }
        CP_COMMIT();
    };
    load_tile(0, 0);
    load_tile(1, 1);

    CP_WAIT2();            // Q resident (tiles 0,1 may be in flight)
    __syncthreads();

    // Q fragments: 4 chunks of K=16
    uint32_t qf[4][4];
    #pragma unroll
    for (int kk = 0; kk < 4; ++kk)
        LDSM4(qf[kk], Qs_u + q_lane + kk * 32);

    float o[8][4];
    #pragma unroll
    for (int d = 0; d < 8; ++d)
        #pragma unroll
        for (int t = 0; t < 4; ++t) o[d][t] = 0.f;
    float m0 = -1e30f, m1 = -1e30f, l0 = 0.f, l1 = 0.f;

    const int NT = Nn / AKT;     // 32
    int cst = 0, lst = 2;
    for (int it = 0; it < NT; ++it) {
        CP_WAIT1();
        __syncthreads();

        if (it + 2 < NT) load_tile(it + 2, lst);
        else             CP_COMMIT();
        lst = (lst == 2) ? 0 : lst + 1;

        const uint32_t Kb = Ks_u + (uint32_t)(cst * AKT * APiH) * 2;
        const uint32_t Vb = Vs_u + (uint32_t)(cst * AKT * APiH) * 2;

        // ---- S = Q K^T  (8 key-chunks of 8) ----
        float s[8][4];
        #pragma unroll
        for (int nf = 0; nf < 8; ++nf) {
            s[nf][0] = 0.f; s[nf][1] = 0.f; s[nf][2] = 0.f; s[nf][3] = 0.f;
            const uint32_t kaddr = Kb + k_lane + nf * 8 * 144;
            #pragma unroll
            for (int kk = 0; kk < 4; ++kk) {
                uint32_t bf[2];
                LDSM2(bf, kaddr + kk * 32);
                mma_f16(s[nf], qf[kk], bf);
            }
            s[nf][0] *= SCALE; s[nf][1] *= SCALE;
            s[nf][2] *= SCALE; s[nf][3] *= SCALE;
        }

        // ---- softmax update ----
        float t0 = -1e30f, t1 = -1e30f;
        #pragma unroll
        for (int nf = 0; nf < 8; ++nf) {
            t0 = fmaxf(t0, fmaxf(s[nf][0], s[nf][1]));
            t1 = fmaxf(t1, fmaxf(s[nf][2], s[nf][3]));
        }
        t0 = fmaxf(t0, __shfl_xor_sync(0xffffffff, t0, 1));
        t0 = fmaxf(t0, __shfl_xor_sync(0xffffffff, t0, 2));
        t1 = fmaxf(t1, __shfl_xor_sync(0xffffffff, t1, 1));
        t1 = fmaxf(t1, __shfl_xor_sync(0xffffffff, t1, 2));
        const float nm0 = fmaxf(m0, t0), nm1 = fmaxf(m1, t1);
        const float c0 = __expf(m0 - nm0), c1 = __expf(m1 - nm1);
        m0 = nm0; m1 = nm1;
        l0 *= c0; l1 *= c1;
        #pragma unroll
        for (int d = 0; d < 8; ++d) {
            o[d][0] *= c0; o[d][1] *= c0;
            o[d][2] *= c1; o[d][3] *= c1;
        }

        // ---- P = exp(S-m) packed directly into k16 A-fragments ----
        uint32_t pa[4][4];
        #pragma unroll
        for (int nf = 0; nf < 8; ++nf) {
            float p0 = __expf(s[nf][0] - m0);
            float p1 = __expf(s[nf][1] - m0);
            float p2 = __expf(s[nf][2] - m1);
            float p3 = __expf(s[nf][3] - m1);
            l0 += p0 + p1;
            l1 += p2 + p3;
            pa[nf >> 1][2 * (nf & 1) + 0] = h2_as_u32(__floats2half2_rn(p0, p1));
            pa[nf >> 1][2 * (nf & 1) + 1] = h2_as_u32(__floats2half2_rn(p2, p3));
        }

        // ---- O += P V  (V^T fragments via ldmatrix.trans) ----
        #pragma unroll
        for (int kt2 = 0; kt2 < 4; ++kt2) {
            const uint32_t vbase = Vb + v_lane + kt2 * 16 * 144;
            #pragma unroll
            for (int df = 0; df < 8; ++df) {
                uint32_t bf[2];
                LDSM2T(bf, vbase + df * 16);
                mma_f16(o[df], pa[kt2], bf);
            }
        }

        cst = (cst == 2) ? 0 : cst + 1;
    }

    l0 += __shfl_xor_sync(0xffffffff, l0, 1);
    l0 += __shfl_xor_sync(0xffffffff, l0, 2);
    l1 += __shfl_xor_sync(0xffffffff, l1, 1);
    l1 += __shfl_xor_sync(0xffffffff, l1, 2);
    const float inv0 = 1.f / l0, inv1 = 1.f / l1;
    const int qr0 = q0 + wq + g;
    const int qr1 = qr0 + 8;
    #pragma unroll
    for (int df = 0; df < 8; ++df) {
        *(__half2*)(ctx + (tok0 + qr0) * Cc_ + hoff + 8 * df + 2 * tig) =
            __floats2half2_rn(o[df][0] * inv0, o[df][1] * inv0);
        *(__half2*)(ctx + (tok0 + qr1) * Cc_ + hoff + 8 * df + 2 * tig) =
            __floats2half2_rn(o[df][2] * inv1, o[df][3] * inv1);
    }
}

// ---------------------------------------------------------------------------
// out[row] = res[row] + LayerNorm(x[row]) * w + b     (row length 1024)
// DUAL=1: also write __half copy to out_h.
// ---------------------------------------------------------------------------
template<int DUAL>
__global__ __launch_bounds__(256)
void ln_residual(const float* __restrict__ x, const float* __restrict__ res,
                 const float* __restrict__ w, const float* __restrict__ bp,
                 float* __restrict__ out, __half* __restrict__ out_h)
{
    __shared__ float red[256];
    const int row = blockIdx.x;
    const int tid = threadIdx.x;
    const size_t base = (size_t)row * Cc_;

    float4 v = *(const float4*)(x + base + tid * 4);
    float s = v.x + v.y + v.z + v.w;
    red[tid] = s;
    __syncthreads();
    #pragma unroll
    for (int off = 128; off > 0; off >>= 1) {
        if (tid < off) red[tid] += red[tid + off];
        __syncthreads();
    }
    const float mu = red[0] * (1.0f / Cc_);
    __syncthreads();

    float d0 = v.x - mu, d1 = v.y - mu, d2 = v.z - mu, d3 = v.w - mu;
    red[tid] = d0*d0 + d1*d1 + d2*d2 + d3*d3;
    __syncthreads();
    #pragma unroll
    for (int off = 128; off > 0; off >>= 1) {
        if (tid < off) red[tid] += red[tid + off];
        __syncthreads();
    }
    const float var  = red[0] * (1.0f / Cc_);
    const float rstd = rsqrtf(var + 1e-5f);

    float4 rv = *(const float4*)(res + base + tid * 4);
    float4 wv = *(const float4*)(w + tid * 4);
    float4 bv = *(const float4*)(bp + tid * 4);
    float4 ov;
    ov.x = rv.x + d0 * rstd * wv.x + bv.x;
    ov.y = rv.y + d1 * rstd * wv.y + bv.y;
    ov.z = rv.z + d2 * rstd * wv.z + bv.z;
    ov.w = rv.w + d3 * rstd * wv.w + bv.w;
    *(float4*)(out + base + tid * 4) = ov;
    if (DUAL == 1) {
        __half2* oh = (__half2*)(out_h + base + tid * 4);
        oh[0] = __floats2half2_rn(ov.x, ov.y);
        oh[1] = __floats2half2_rn(ov.z, ov.w);
    }
}

// ---------------------------------------------------------------------------
// Launch
// ---------------------------------------------------------------------------
extern "C" void kernel_launch(void* const* d_in, const int* in_sizes, int n_in,
                              void* d_out, int out_size)
{
    const float* x      = (const float*)d_in[0];
    const float* qkv_w  = (const float*)d_in[1];
    const float* proj_w = (const float*)d_in[2];
    const float* proj_b = (const float*)d_in[3];
    const float* ln1_w  = (const float*)d_in[4];
    const float* ln1_b  = (const float*)d_in[5];
    const float* fc1_w  = (const float*)d_in[6];
    const float* fc1_b  = (const float*)d_in[7];
    const float* fc2_w  = (const float*)d_in[8];
    const float* fc2_b  = (const float*)d_in[9];
    const float* ln2_w  = (const float*)d_in[10];
    const float* ln2_b  = (const float*)d_in[11];
    float* out = (float*)d_out;

    float *res, *mlp;
    __half *qkv, *ctx, *resr, *hbuf, *xh, *w1, *w2, *w3, *w4;
    cudaGetSymbolAddress((void**)&qkv,  g_qkv);
    cudaGetSymbolAddress((void**)&ctx,  g_ctx);
    cudaGetSymbolAddress((void**)&res,  g_res);
    cudaGetSymbolAddress((void**)&resr, g_resr);
    cudaGetSymbolAddress((void**)&hbuf, g_h);
    cudaGetSymbolAddress((void**)&mlp,  g_mlp);
    cudaGetSymbolAddress((void**)&xh,   g_xh);
    cudaGetSymbolAddress((void**)&w1,   g_w1);
    cudaGetSymbolAddress((void**)&w2,   g_w2);
    cudaGetSymbolAddress((void**)&w3,   g_w3);
    cudaGetSymbolAddress((void**)&w4,   g_w4);

    cudaFuncSetAttribute(h_gemm<0,0>,
        cudaFuncAttributeMaxDynamicSharedMemorySize, GEMM_SMEM);
    cudaFuncSetAttribute(h_gemm<0,2>,
        cudaFuncAttributeMaxDynamicSharedMemorySize, GEMM_SMEM);
    cudaFuncSetAttribute(h_gemm<1,2>,
        cudaFuncAttributeMaxDynamicSharedMemorySize, GEMM_SMEM);
    cudaFuncSetAttribute(attn_h,
        cudaFuncAttributeMaxDynamicSharedMemorySize, ATT_SMEM);

    auto pgrid = [](int M, int N) {
        int nt = (M / GBM) * (N / GBN);
        return nt < PERS_CTAS ? nt : PERS_CTAS;
    };

    // 0) one fused fp16 conversion pass for all GEMM operands
    to_half_all<<<CONV_BLOCKS, 256>>>(x, qkv_w, proj_w, fc1_w, fc2_w,
                                      xh, w1, w2, w3, w4);

    // 1) qkv = x @ qkv_w^T  (half out)
    h_gemm<0,2><<<pgrid(MTOK, 3 * Cc_), 256, GEMM_SMEM>>>(
        xh, w1, nullptr, qkv, MTOK, 3 * Cc_, Cc_);
    // 2) attention -> ctx (half)
    attn_h<<<dim3(Nn / AQ, Hh, Bb), 256, ATT_SMEM>>>(qkv, ctx);
    // 3) res = ctx @ proj_w^T + proj_b  (fp32 residual base)
    h_gemm<0,0><<<pgrid(MTOK, Cc_), 256, GEMM_SMEM>>>(
        ctx, w2, proj_b, res, MTOK, Cc_, Cc_);
    // 4) res = res + LN(res); also half copy resr
    ln_residual<1><<<MTOK, 256>>>(res, res, ln1_w, ln1_b, res, resr);
    // 5) h = gelu(resr @ fc1_w^T + fc1_b)  (half out)
    h_gemm<1,2><<<pgrid(MTOK, HID), 256, GEMM_SMEM>>>(
        resr, w3, fc1_b, hbuf, MTOK, HID, Cc_);
    // 6) mlp = h @ fc2_w^T + fc2_b  (fp32 out)
    h_gemm<0,0><<<pgrid(MTOK, Cc_), 256, GEMM_SMEM>>>(
        hbuf, w4, fc2_b, mlp, MTOK, Cc_, HID);
    // 7) out = res + LN(mlp)
    ln_residual<0><<<MTOK, 256>>>(mlp, res, ln2_w, ln2_b, out, nullptr);
}